// round 7
// baseline (speedup 1.0000x reference)
#include <cuda_runtime.h>

// SparseEmbedding: out[b, :] = sum_n vals[b,n] * kernel[idx[b,n], :] + bias
// BATCH=4096, NNZ=32, VOCAB=1e6, DIM=64. float32 everywhere, idx int32.
//
// R6: every LSU-path variant (LDG scalar/wide/batched, cp.async) pins at
// ~3.2TB/s with nothing saturated -> per-SM outstanding-miss tracking cap
// (~248 lines in flight/SM). The TMA bulk-copy engine (cp.async.bulk /
// UBLKCP) tracks completion via mbarrier transactions, not LSU MSHRs, and
// reaches the LTS cap. Each lane issues one 256B bulk copy for its nnz row
// into a per-warp SMEM buffer; per-warp mbarrier expect_tx(8KB); reduce.

#define BATCH 4096
#define NNZ   32
#define DIM   64
#define WARPS_PER_CTA 4
#define ROW_BYTES 256

__global__ void __launch_bounds__(WARPS_PER_CTA * 32) sparse_embedding_kernel(
    const int*   __restrict__ idx,
    const float* __restrict__ vals,
    const float* __restrict__ table,
    const float* __restrict__ bias,
    float*       __restrict__ out)
{
    __shared__ __align__(256) float buf[WARPS_PER_CTA][NNZ * DIM];
    __shared__ __align__(8) unsigned long long mbar[WARPS_PER_CTA];

    const int warp  = threadIdx.x >> 5;
    const int lane  = threadIdx.x & 31;
    const int gwarp = blockIdx.x * WARPS_PER_CTA + warp;   // batch row

    unsigned mbar_addr;
    {
        unsigned long long* p = &mbar[warp];
        asm("{ .reg .u64 t; cvta.to.shared.u64 t, %1; cvt.u32.u64 %0, t; }"
            : "=r"(mbar_addr) : "l"(p));
    }

    // Per-warp mbarrier: 1 arrival (the expect_tx) + 8KB of transactions.
    if (lane == 0) {
        asm volatile("mbarrier.init.shared.b64 [%0], 1;" :: "r"(mbar_addr) : "memory");
        asm volatile("fence.proxy.async.shared::cta;" ::: "memory");
        asm volatile("mbarrier.arrive.expect_tx.shared.b64 _, [%0], %1;"
                     :: "r"(mbar_addr), "r"(NNZ * ROW_BYTES) : "memory");
    }
    __syncwarp();

    // Each lane: one 256B bulk copy (TMA engine) for its nnz row.
    const int   my_idx = idx[gwarp * NNZ + lane];
    const float my_val = vals[gwarp * NNZ + lane];
    {
        const float* src = table + (size_t)my_idx * DIM;
        unsigned dst;
        float* d = &buf[warp][lane * DIM];
        asm("{ .reg .u64 t; cvta.to.shared.u64 t, %1; cvt.u32.u64 %0, t; }"
            : "=r"(dst) : "l"(d));
        asm volatile(
            "cp.async.bulk.shared::cta.global.mbarrier::complete_tx::bytes "
            "[%0], [%1], %2, [%3];"
            :: "r"(dst), "l"(src), "r"(ROW_BYTES), "r"(mbar_addr) : "memory");
    }

    // Wait for all 32 copies of this warp (phase parity 0).
    {
        unsigned done;
        asm volatile(
            "{\n\t.reg .pred p;\n\t"
            "mbarrier.try_wait.parity.acquire.cta.shared::cta.b64 p, [%1], 0;\n\t"
            "selp.b32 %0, 1, 0, p;\n\t}"
            : "=r"(done) : "r"(mbar_addr) : "memory");
        if (!done) {
            asm volatile(
                "{\n\t.reg .pred P1;\n\t"
                "WL_%=:\n\t"
                "mbarrier.try_wait.parity.acquire.cta.shared::cta.b64 P1, [%0], 0, 0x989680;\n\t"
                "@P1 bra.uni WD_%=;\n\t"
                "bra.uni WL_%=;\n\t"
                "WD_%=:\n\t}"
                :: "r"(mbar_addr) : "memory");
        }
    }

    // Reduce from SMEM. Lane l owns dims [2l, 2l+1].
    float2 acc = reinterpret_cast<const float2*>(bias)[lane];
#pragma unroll
    for (int n = 0; n < NNZ; ++n) {
        const float v = __shfl_sync(0xffffffffu, my_val, n);
        const float2 kv = *reinterpret_cast<const float2*>(
            &buf[warp][n * DIM + lane * 2]);
        acc.x = fmaf(v, kv.x, acc.x);
        acc.y = fmaf(v, kv.y, acc.y);
    }

    reinterpret_cast<float2*>(out + (size_t)gwarp * DIM)[lane] = acc;
}

extern "C" void kernel_launch(void* const* d_in, const int* in_sizes, int n_in,
                              void* d_out, int out_size)
{
    const int*   idx   = (const int*)  d_in[0];
    const float* vals  = (const float*)d_in[1];
    const float* table = (const float*)d_in[2];
    const float* bias  = (const float*)d_in[3];
    float*       out   = (float*)d_out;

    const int threads = WARPS_PER_CTA * 32;          // 128
    const int blocks  = BATCH / WARPS_PER_CTA;       // 1024
    sparse_embedding_kernel<<<blocks, threads>>>(idx, vals, table, bias, out);
}

// round 8
// speedup vs baseline: 1.1882x; 1.1882x over previous
#include <cuda_runtime.h>

// SparseEmbedding: out[b, :] = sum_n vals[b,n] * kernel[idx[b,n], :] + bias
// BATCH=4096, NNZ=32, VOCAB=1e6, DIM=64. float32 everywhere, idx int32.
//
// R7: dual-path gather. All single-path variants (LDG, cp.async, TMA bulk)
// plateau at ~3TB/s with nothing saturated -> suspect per-path concurrency
// caps of similar size. This kernel drives BOTH engines concurrently:
//   nnz 16-31: cp.async.bulk (TMA engine) -> SMEM, issued first
//   nnz  0-15: __ldcg (LSU/L2 path) with FMA accumulation, overlapping TMA
// then waits on the per-warp mbarrier and accumulates the SMEM half.

#define BATCH 4096
#define NNZ   32
#define DIM   64
#define WARPS_PER_CTA 4
#define ROW_BYTES 256
#define TMA_ROWS 16            // nnz rows 16..31 go via TMA
#define LDG_ROWS 16            // nnz rows 0..15 go via LDG

__global__ void __launch_bounds__(WARPS_PER_CTA * 32) sparse_embedding_kernel(
    const int*   __restrict__ idx,
    const float* __restrict__ vals,
    const float* __restrict__ table,
    const float* __restrict__ bias,
    float*       __restrict__ out)
{
    __shared__ __align__(256) float buf[WARPS_PER_CTA][TMA_ROWS * DIM]; // 16KB
    __shared__ __align__(8) unsigned long long mbar[WARPS_PER_CTA];

    const int warp  = threadIdx.x >> 5;
    const int lane  = threadIdx.x & 31;
    const int gwarp = blockIdx.x * WARPS_PER_CTA + warp;   // batch row

    unsigned mbar_addr;
    {
        unsigned long long* p = &mbar[warp];
        asm("{ .reg .u64 t; cvta.to.shared.u64 t, %1; cvt.u32.u64 %0, t; }"
            : "=r"(mbar_addr) : "l"(p));
    }

    const int   my_idx = idx[gwarp * NNZ + lane];
    const float my_val = vals[gwarp * NNZ + lane];

    // Per-warp mbarrier: expect 16 rows x 256B = 4KB of transactions.
    if (lane == 0) {
        asm volatile("mbarrier.init.shared.b64 [%0], 1;" :: "r"(mbar_addr) : "memory");
        asm volatile("fence.proxy.async.shared::cta;" ::: "memory");
        asm volatile("mbarrier.arrive.expect_tx.shared.b64 _, [%0], %1;"
                     :: "r"(mbar_addr), "r"(TMA_ROWS * ROW_BYTES) : "memory");
    }
    __syncwarp();

    // Phase 1a: lanes 16..31 issue one 256B TMA bulk copy for their own nnz
    // slot into buf[warp][(lane-16)*64]. Fire these FIRST.
    if (lane >= 16) {
        const float* src = table + (size_t)my_idx * DIM;
        unsigned dst;
        float* d = &buf[warp][(lane - 16) * DIM];
        asm("{ .reg .u64 t; cvta.to.shared.u64 t, %1; cvt.u32.u64 %0, t; }"
            : "=r"(dst) : "l"(d));
        asm volatile(
            "cp.async.bulk.shared::cta.global.mbarrier::complete_tx::bytes "
            "[%0], [%1], %2, [%3];"
            :: "r"(dst), "l"(src), "r"(ROW_BYTES), "r"(mbar_addr) : "memory");
    }

    // Phase 1b: LDG half (nnz 0..15) via L2-direct loads, overlapping the TMA
    // copies. Lane l owns dims [2l, 2l+1].
    float2 acc = reinterpret_cast<const float2*>(bias)[lane];
#pragma unroll
    for (int n = 0; n < LDG_ROWS; ++n) {
        const int   id = __shfl_sync(0xffffffffu, my_idx, n);
        const float v  = __shfl_sync(0xffffffffu, my_val, n);
        const float2 kv = __ldcg(reinterpret_cast<const float2*>(
            table + (size_t)id * DIM) + lane);
        acc.x = fmaf(v, kv.x, acc.x);
        acc.y = fmaf(v, kv.y, acc.y);
    }

    // Phase 2: wait for the TMA half (phase parity 0).
    {
        unsigned done;
        asm volatile(
            "{\n\t.reg .pred p;\n\t"
            "mbarrier.try_wait.parity.acquire.cta.shared::cta.b64 p, [%1], 0;\n\t"
            "selp.b32 %0, 1, 0, p;\n\t}"
            : "=r"(done) : "r"(mbar_addr) : "memory");
        if (!done) {
            asm volatile(
                "{\n\t.reg .pred P1;\n\t"
                "WL_%=:\n\t"
                "mbarrier.try_wait.parity.acquire.cta.shared::cta.b64 P1, [%0], 0, 0x989680;\n\t"
                "@P1 bra.uni WD_%=;\n\t"
                "bra.uni WL_%=;\n\t"
                "WD_%=:\n\t}"
                :: "r"(mbar_addr) : "memory");
        }
    }

    // Phase 3: accumulate the TMA half from SMEM.
#pragma unroll
    for (int n = 0; n < TMA_ROWS; ++n) {
        const float v = __shfl_sync(0xffffffffu, my_val, 16 + n);
        const float2 kv = *reinterpret_cast<const float2*>(
            &buf[warp][n * DIM + lane * 2]);
        acc.x = fmaf(v, kv.x, acc.x);
        acc.y = fmaf(v, kv.y, acc.y);
    }

    reinterpret_cast<float2*>(out + (size_t)gwarp * DIM)[lane] = acc;
}

extern "C" void kernel_launch(void* const* d_in, const int* in_sizes, int n_in,
                              void* d_out, int out_size)
{
    const int*   idx   = (const int*)  d_in[0];
    const float* vals  = (const float*)d_in[1];
    const float* table = (const float*)d_in[2];
    const float* bias  = (const float*)d_in[3];
    float*       out   = (float*)d_out;

    const int threads = WARPS_PER_CTA * 32;          // 128
    const int blocks  = BATCH / WARPS_PER_CTA;       // 1024
    sparse_embedding_kernel<<<blocks, threads>>>(idx, vals, table, bias, out);
}

// round 9
// speedup vs baseline: 1.2385x; 1.0423x over previous
#include <cuda_runtime.h>

// SparseEmbedding: out[b, :] = sum_n vals[b,n] * kernel[idx[b,n], :] + bias
// BATCH=4096, NNZ=32, VOCAB=1e6, DIM=64. float32 everywhere, idx int32.
//
// R8: all HW paths (LDG/L1, LDGSTS, TMA bulk, dual-path) pin at ~3.2-3.7TB/s
// with nothing saturated and warm==cold -> limiter is downstream of L2 slices
// (cross-die fabric / short-kernel amortization), i.e. near the pattern floor.
// This round: cleanest max-demand kernel. One warp per row, all 32 gathers
// front-batched into registers (MLP=32/warp) via __ldcg (bypass useless L1
// lookup), 256-thread CTAs for wave balance, bias folded into acc init.

#define BATCH 4096
#define NNZ   32
#define DIM   64

__global__ void __launch_bounds__(256, 1) sparse_embedding_kernel(
    const int*   __restrict__ idx,
    const float* __restrict__ vals,
    const float* __restrict__ table,
    const float* __restrict__ bias,
    float*       __restrict__ out)
{
    const int gwarp = (blockIdx.x * blockDim.x + threadIdx.x) >> 5;
    const int lane  = threadIdx.x & 31;

    // Each lane holds one (idx, val) pair for this row; broadcast via shfl.
    const int   my_idx = __ldg(idx  + gwarp * NNZ + lane);
    const float my_val = __ldg(vals + gwarp * NNZ + lane);

    // Phase 1: issue ALL 32 gather loads before any consumer.
    // .cg -> L2-direct, no L1 lookup (zero reuse across warps anyway).
    float2 kv[NNZ];
#pragma unroll
    for (int n = 0; n < NNZ; ++n) {
        const int id = __shfl_sync(0xffffffffu, my_idx, n);
        kv[n] = __ldcg(reinterpret_cast<const float2*>(
            table + (size_t)id * DIM) + lane);
    }

    // Phase 2: accumulate (bias folded into init).
    float2 acc = __ldg(reinterpret_cast<const float2*>(bias) + lane);
#pragma unroll
    for (int n = 0; n < NNZ; ++n) {
        const float v = __shfl_sync(0xffffffffu, my_val, n);
        acc.x = fmaf(v, kv[n].x, acc.x);
        acc.y = fmaf(v, kv[n].y, acc.y);
    }

    reinterpret_cast<float2*>(out + (size_t)gwarp * DIM)[lane] = acc;
}

extern "C" void kernel_launch(void* const* d_in, const int* in_sizes, int n_in,
                              void* d_out, int out_size)
{
    const int*   idx   = (const int*)  d_in[0];
    const float* vals  = (const float*)d_in[1];
    const float* table = (const float*)d_in[2];
    const float* bias  = (const float*)d_in[3];
    float*       out   = (float*)d_out;

    // 4096 warps, 8 warps per 256-thread CTA -> 512 CTAs (3-4 waves of
    // co-resident CTAs across 148 SMs; divides evenly, no partial wave).
    const int threads = 256;
    const int blocks  = (BATCH * 32) / threads;
    sparse_embedding_kernel<<<blocks, threads>>>(idx, vals, table, bias, out);
}